// round 2
// baseline (speedup 1.0000x reference)
#include <cuda_runtime.h>
#include <math.h>

// AlphaModel: relation-gated blend of parent/child categorical distributions.
// HBM-bound streaming kernel: 400 MB traffic over 10M edges.
// R2: vectorized shared-mem param gathers (float4), fast-math MUFU intrinsics,
// no softmax max-subtraction (scores bounded), fewer regs -> higher occupancy.

#define N_RELS 64
#define BLOCK 256

__device__ __forceinline__ void compute_edge(
    const float p0, const float p1, const float p2,
    const float c0, const float c1, const float c2,
    int r,
    const float4* __restrict__ sP,   // [N_RELS*4]: rows 0..2 of M[r] (xyz used), row 3 = beta[r]
    float zeps, float sf,
    float& o0, float& o1, float& o2)
{
    const float4* Pr = sP + (r << 2);
    float4 m0 = Pr[0];
    float4 m1 = Pr[1];
    float4 m2 = Pr[2];
    float4 bb = Pr[3];

    // scores = M[r] @ child_probs (no max-sub: scores are bounded, __expf safe)
    float s0 = fmaf(m0.x, c0, fmaf(m0.y, c1, m0.z * c2));
    float s1 = fmaf(m1.x, c0, fmaf(m1.y, c1, m1.z * c2));
    float s2 = fmaf(m2.x, c0, fmaf(m2.y, c1, m2.z * c2));

    float e0 = __expf(s0);
    float e1 = __expf(s1);
    float e2 = __expf(s2);
    float inv = __fdividef(1.0f, e0 + e1 + e2);
    float ch0 = e0 * inv, ch1 = e1 * inv, ch2 = e2 * inv;

    // alpha = p + b*(ch - p)
    float a0 = fmaf(bb.x, ch0 - p0, p0);
    float a1 = fmaf(bb.y, ch1 - p1, p1);
    float a2 = fmaf(bb.z, ch2 - p2, p2);

    // entropy of clipped renormalized blend
    float z0 = fmaxf(zeps, p0 + ch0);
    float z1 = fmaxf(zeps, p1 + ch1);
    float z2 = fmaxf(zeps, p2 + ch2);
    float izs = __fdividef(1.0f, z0 + z1 + z2);
    z0 *= izs; z1 *= izs; z2 *= izs;
    float ent = -(z0 * __logf(z0) + z1 * __logf(z1) + z2 * __logf(z2));

    // cosine similarity parent vs softmaxed child
    float dot = fmaf(p0, ch0, fmaf(p1, ch1, p2 * ch2));
    float pp  = fmaf(p0, p0, fmaf(p1, p1, p2 * p2));
    float cc  = fmaf(ch0, ch0, fmaf(ch1, ch1, ch2 * ch2));
    float n2  = pp * cc;
    float invn = (n2 == 0.0f) ? 1.0f : rsqrtf(n2);
    float cosv = fmaf(dot, invn, 1.1f);

    float scale = __fdividef(sf * cosv, ent);
    o0 = a0 * scale;
    o1 = a1 * scale;
    o2 = a2 * scale;
}

__global__ void __launch_bounds__(BLOCK)
alpha_model_kernel(const float* __restrict__ prnt,
                   const float* __restrict__ child,
                   const int*   __restrict__ rels,
                   const float* __restrict__ Mg,
                   const float* __restrict__ betag,
                   const float* __restrict__ zeps_p,
                   const float* __restrict__ sf_p,
                   float* __restrict__ out,
                   int E)
{
    // packed params: per rel, 4x float4 = {M row0, M row1, M row2, beta}
    __shared__ float4 sP[N_RELS * 4];
    {
        float* s = reinterpret_cast<float*>(sP);
        for (int i = threadIdx.x; i < N_RELS * 16; i += BLOCK) {
            int r = i >> 4;       // rel
            int k = i & 15;       // slot within the 16-float record
            float v = 0.0f;
            if (k < 9)            v = Mg[r * 9 + k];          // rows 0..2 packed at x,y,z? no:
            // we need row-major with pad: slots 0..2=row0, 4..6=row1, 8..10=row2, 12..14=beta
            s[i] = v; // placeholder, overwritten below
        }
    }
    __syncthreads();
    // simpler correct fill (few enough elements that redundancy is free)
    if (threadIdx.x < N_RELS) {
        int r = threadIdx.x;
        float4 v0, v1, v2, v3;
        v0.x = Mg[r*9+0]; v0.y = Mg[r*9+1]; v0.z = Mg[r*9+2]; v0.w = 0.f;
        v1.x = Mg[r*9+3]; v1.y = Mg[r*9+4]; v1.z = Mg[r*9+5]; v1.w = 0.f;
        v2.x = Mg[r*9+6]; v2.y = Mg[r*9+7]; v2.z = Mg[r*9+8]; v2.w = 0.f;
        v3.x = betag[r*3+0]; v3.y = betag[r*3+1]; v3.z = betag[r*3+2]; v3.w = 0.f;
        sP[(r<<2)+0] = v0;
        sP[(r<<2)+1] = v1;
        sP[(r<<2)+2] = v2;
        sP[(r<<2)+3] = v3;
    }
    __syncthreads();

    const float zeps = __ldg(zeps_p);
    const float sf   = __ldg(sf_p);

    int quad  = blockIdx.x * BLOCK + threadIdx.x;  // group of 4 edges
    int nquad = (E + 3) >> 2;
    if (quad >= nquad) return;
    int e0 = quad << 2;

    if (e0 + 4 <= E) {
        const float4* p4 = reinterpret_cast<const float4*>(prnt  + (size_t)e0 * 3);
        const float4* c4 = reinterpret_cast<const float4*>(child + (size_t)e0 * 3);
        const int4*   r4 = reinterpret_cast<const int4*>(rels + e0);

        float4 pa = p4[0], pb = p4[1], pc = p4[2];
        float4 ca = c4[0], cb = c4[1], cc = c4[2];
        int4 rv = r4[0];

        float pv[12] = {pa.x, pa.y, pa.z, pa.w, pb.x, pb.y, pb.z, pb.w, pc.x, pc.y, pc.z, pc.w};
        float cv[12] = {ca.x, ca.y, ca.z, ca.w, cb.x, cb.y, cb.z, cb.w, cc.x, cc.y, cc.z, cc.w};
        int   rr[4]  = {rv.x, rv.y, rv.z, rv.w};

        float ov[12];
#pragma unroll
        for (int j = 0; j < 4; j++) {
            compute_edge(pv[3*j], pv[3*j+1], pv[3*j+2],
                         cv[3*j], cv[3*j+1], cv[3*j+2],
                         rr[j], sP, zeps, sf,
                         ov[3*j], ov[3*j+1], ov[3*j+2]);
        }

        float4* o4 = reinterpret_cast<float4*>(out + (size_t)e0 * 3);
        o4[0] = make_float4(ov[0], ov[1], ov[2],  ov[3]);
        o4[1] = make_float4(ov[4], ov[5], ov[6],  ov[7]);
        o4[2] = make_float4(ov[8], ov[9], ov[10], ov[11]);
    } else {
        for (int e = e0; e < E; e++) {
            float o0, o1, o2;
            compute_edge(prnt[3*e], prnt[3*e+1], prnt[3*e+2],
                         child[3*e], child[3*e+1], child[3*e+2],
                         rels[e], sP, zeps, sf, o0, o1, o2);
            out[3*e]   = o0;
            out[3*e+1] = o1;
            out[3*e+2] = o2;
        }
    }
}

extern "C" void kernel_launch(void* const* d_in, const int* in_sizes, int n_in,
                              void* d_out, int out_size)
{
    // input order: var_sfx, prnt_probs, child_probs, rels, M, beta, z_epsilon, scale_factor
    const float* prnt  = (const float*)d_in[1];
    const float* child = (const float*)d_in[2];
    const int*   rels  = (const int*)d_in[3];
    const float* Mg    = (const float*)d_in[4];
    const float* betag = (const float*)d_in[5];
    const float* zeps  = (const float*)d_in[6];
    const float* sf    = (const float*)d_in[7];
    float* out = (float*)d_out;

    int E = in_sizes[1] / 3;
    int nquad = (E + 3) >> 2;
    int grid = (nquad + BLOCK - 1) / BLOCK;

    alpha_model_kernel<<<grid, BLOCK>>>(prnt, child, rels, Mg, betag, zeps, sf, out, E);
}

// round 3
// speedup vs baseline: 1.5847x; 1.5847x over previous
#include <cuda_runtime.h>
#include <math.h>

// AlphaModel: relation-gated blend of parent/child categorical distributions.
// HBM-bound streaming: 400 MB over 10M edges; roofline floor ~60us.
// R3: R1's scalar conflict-free shared layout (strides 9/3, gcd(.,32)=1)
//     + R2's fast-math MUFU intrinsics. (R2's float4 LDS gathers bank-conflicted.)

#define N_RELS 64
#define BLOCK 256

__device__ __forceinline__ void compute_edge(
    const float p0, const float p1, const float p2,
    const float c0, const float c1, const float c2,
    int r,
    const float* __restrict__ sM, const float* __restrict__ sB,
    float zeps, float sf,
    float& o0, float& o1, float& o2)
{
    const float* Mr = sM + r * 9;
    const float* Br = sB + r * 3;

    // scores = M[r] @ child_probs (no max-sub: scores bounded, __expf safe)
    float s0 = fmaf(Mr[0], c0, fmaf(Mr[1], c1, Mr[2] * c2));
    float s1 = fmaf(Mr[3], c0, fmaf(Mr[4], c1, Mr[5] * c2));
    float s2 = fmaf(Mr[6], c0, fmaf(Mr[7], c1, Mr[8] * c2));

    float e0 = __expf(s0);
    float e1 = __expf(s1);
    float e2 = __expf(s2);
    float inv = __fdividef(1.0f, e0 + e1 + e2);
    float ch0 = e0 * inv, ch1 = e1 * inv, ch2 = e2 * inv;

    // alpha = p + b*(ch - p)
    float a0 = fmaf(Br[0], ch0 - p0, p0);
    float a1 = fmaf(Br[1], ch1 - p1, p1);
    float a2 = fmaf(Br[2], ch2 - p2, p2);

    // entropy of clipped renormalized blend
    float z0 = fmaxf(zeps, p0 + ch0);
    float z1 = fmaxf(zeps, p1 + ch1);
    float z2 = fmaxf(zeps, p2 + ch2);
    float izs = __fdividef(1.0f, z0 + z1 + z2);
    z0 *= izs; z1 *= izs; z2 *= izs;
    float ent = -(z0 * __logf(z0) + z1 * __logf(z1) + z2 * __logf(z2));

    // cosine similarity parent vs softmaxed child
    float dot = fmaf(p0, ch0, fmaf(p1, ch1, p2 * ch2));
    float pp  = fmaf(p0, p0, fmaf(p1, p1, p2 * p2));
    float cc  = fmaf(ch0, ch0, fmaf(ch1, ch1, ch2 * ch2));
    float n2  = pp * cc;
    float invn = (n2 == 0.0f) ? 1.0f : rsqrtf(n2);
    float cosv = fmaf(dot, invn, 1.1f);

    float scale = __fdividef(sf * cosv, ent);
    o0 = a0 * scale;
    o1 = a1 * scale;
    o2 = a2 * scale;
}

__global__ void __launch_bounds__(BLOCK)
alpha_model_kernel(const float* __restrict__ prnt,
                   const float* __restrict__ child,
                   const int*   __restrict__ rels,
                   const float* __restrict__ Mg,
                   const float* __restrict__ betag,
                   const float* __restrict__ zeps_p,
                   const float* __restrict__ sf_p,
                   float* __restrict__ out,
                   int E)
{
    __shared__ float sM[N_RELS * 9];
    __shared__ float sB[N_RELS * 3];
    for (int i = threadIdx.x; i < N_RELS * 9; i += BLOCK) sM[i] = Mg[i];
    for (int i = threadIdx.x; i < N_RELS * 3; i += BLOCK) sB[i] = betag[i];
    __syncthreads();

    const float zeps = __ldg(zeps_p);
    const float sf   = __ldg(sf_p);

    int quad  = blockIdx.x * BLOCK + threadIdx.x;  // group of 4 edges
    int nquad = (E + 3) >> 2;
    if (quad >= nquad) return;
    int e0 = quad << 2;

    if (e0 + 4 <= E) {
        const float4* p4 = reinterpret_cast<const float4*>(prnt  + (size_t)e0 * 3);
        const float4* c4 = reinterpret_cast<const float4*>(child + (size_t)e0 * 3);
        const int4*   r4 = reinterpret_cast<const int4*>(rels + e0);

        float4 pa = p4[0], pb = p4[1], pc = p4[2];
        float4 ca = c4[0], cb = c4[1], cc = c4[2];
        int4 rv = r4[0];

        float pv[12] = {pa.x, pa.y, pa.z, pa.w, pb.x, pb.y, pb.z, pb.w, pc.x, pc.y, pc.z, pc.w};
        float cv[12] = {ca.x, ca.y, ca.z, ca.w, cb.x, cb.y, cb.z, cb.w, cc.x, cc.y, cc.z, cc.w};
        int   rr[4]  = {rv.x, rv.y, rv.z, rv.w};

        float ov[12];
#pragma unroll
        for (int j = 0; j < 4; j++) {
            compute_edge(pv[3*j], pv[3*j+1], pv[3*j+2],
                         cv[3*j], cv[3*j+1], cv[3*j+2],
                         rr[j], sM, sB, zeps, sf,
                         ov[3*j], ov[3*j+1], ov[3*j+2]);
        }

        float4* o4 = reinterpret_cast<float4*>(out + (size_t)e0 * 3);
        o4[0] = make_float4(ov[0], ov[1], ov[2],  ov[3]);
        o4[1] = make_float4(ov[4], ov[5], ov[6],  ov[7]);
        o4[2] = make_float4(ov[8], ov[9], ov[10], ov[11]);
    } else {
        for (int e = e0; e < E; e++) {
            float o0, o1, o2;
            compute_edge(prnt[3*e], prnt[3*e+1], prnt[3*e+2],
                         child[3*e], child[3*e+1], child[3*e+2],
                         rels[e], sM, sB, zeps, sf, o0, o1, o2);
            out[3*e]   = o0;
            out[3*e+1] = o1;
            out[3*e+2] = o2;
        }
    }
}

extern "C" void kernel_launch(void* const* d_in, const int* in_sizes, int n_in,
                              void* d_out, int out_size)
{
    // input order: var_sfx, prnt_probs, child_probs, rels, M, beta, z_epsilon, scale_factor
    const float* prnt  = (const float*)d_in[1];
    const float* child = (const float*)d_in[2];
    const int*   rels  = (const int*)d_in[3];
    const float* Mg    = (const float*)d_in[4];
    const float* betag = (const float*)d_in[5];
    const float* zeps  = (const float*)d_in[6];
    const float* sf    = (const float*)d_in[7];
    float* out = (float*)d_out;

    int E = in_sizes[1] / 3;
    int nquad = (E + 3) >> 2;
    int grid = (nquad + BLOCK - 1) / BLOCK;

    alpha_model_kernel<<<grid, BLOCK>>>(prnt, child, rels, Mg, betag, zeps, sf, out, E);
}